// round 11
// baseline (speedup 1.0000x reference)
#include <cuda_runtime.h>
#include <math.h>

// Problem constants
#define NIMG 72                 // BATCH(8) * NUM_MODES(3) * NUM_WL(3)
#define H 512
#define IMG_ELEMS (H * H)       // 262144
#define NWL 3
#define NUM_LAYERS 5

// ---------------------------------------------------------------------------
// Scratch (no allocations allowed -> __device__ globals)
// ---------------------------------------------------------------------------
__device__ float2 g_bufA[NIMG * IMG_ELEMS];              // ~151 MB
__device__ float2 g_bufB[NIMG * IMG_ELEMS];              // ~151 MB
__device__ float2 g_PLT [NWL * IMG_ELEMS];               // prop_layer*(1/512), TRANSPOSED [w][b][a]
__device__ float2 g_PLDT[NWL * IMG_ELEMS];               // prop_layer*prop_det*(1/512), transposed
__device__ float2 g_ME  [NUM_LAYERS * NWL * IMG_ELEMS];  // exp(i*mask); layers>=1 pre-scaled 1/512 (31.5 MB)
__device__ float2 g_tw2 [8 * 64];                        // tw2[r][j] = exp(-2*pi*i*r*j/512)

// ---------------------------------------------------------------------------
// Complex helpers
// ---------------------------------------------------------------------------
__device__ __forceinline__ float2 cmul(float2 a, float2 b) {
    return make_float2(a.x * b.x - a.y * b.y, a.x * b.y + a.y * b.x);
}
// multiply by b (INV=0) or conj(b) (INV=1); negations fold into FMA operands
template <int INV>
__device__ __forceinline__ float2 cmul_t(float2 a, float2 b) {
    return INV ? make_float2(a.x * b.x + a.y * b.y, a.y * b.x - a.x * b.y)
               : make_float2(a.x * b.x - a.y * b.y, a.x * b.y + a.y * b.x);
}
__device__ __forceinline__ float2 cadd(float2 a, float2 b) { return make_float2(a.x + b.x, a.y + b.y); }
__device__ __forceinline__ float2 csub(float2 a, float2 b) { return make_float2(a.x - b.x, a.y - b.y); }

// multiply by -i (forward, INV=0) or +i (inverse, INV=1)
template <int INV>
__device__ __forceinline__ float2 rot90(float2 a) {
    return INV ? make_float2(-a.y, a.x) : make_float2(a.y, -a.x);
}

// Group-local barrier: 2 warps (64 threads) of one FFT group. Named HW
// barrier ids 1..8 (id 0 belongs to __syncthreads).
__device__ __forceinline__ void bar64(int id) {
    asm volatile("bar.sync %0, 64;" :: "r"(id) : "memory");
}

// Natural-order 8-point DFT (DIT). Input v[n] time order, output v[k] freq order.
template <int INV>
__device__ __forceinline__ void fft8(float2 v[8]) {
    float2 t0 = cadd(v[0], v[4]), t1 = csub(v[0], v[4]);
    float2 t2 = cadd(v[2], v[6]), t3 = rot90<INV>(csub(v[2], v[6]));
    float2 E0 = cadd(t0, t2), E2 = csub(t0, t2);
    float2 E1 = cadd(t1, t3), E3 = csub(t1, t3);
    float2 u0 = cadd(v[1], v[5]), u1 = csub(v[1], v[5]);
    float2 u2 = cadd(v[3], v[7]), u3 = rot90<INV>(csub(v[3], v[7]));
    float2 O0 = cadd(u0, u2), O2 = csub(u0, u2);
    float2 O1 = cadd(u1, u3), O3 = csub(u1, u3);
    const float r2 = 0.70710678118654752440f;
    float2 w1 = make_float2(r2, INV ? r2 : -r2);
    float2 w3 = make_float2(-r2, INV ? r2 : -r2);
    O1 = cmul(O1, w1);
    O2 = rot90<INV>(O2);
    O3 = cmul(O3, w3);
    v[0] = cadd(E0, O0); v[4] = csub(E0, O0);
    v[1] = cadd(E1, O1); v[5] = csub(E1, O1);
    v[2] = cadd(E2, O2); v[6] = csub(E2, O2);
    v[3] = cadd(E3, O3); v[7] = csub(E3, O3);
}

// Shared-memory padding: kills stage-0 store bank conflicts
#define PAD(i) ((i) + ((i) >> 3))

// 512-point Stockham FFT, radix-8, 3 stages, 64 threads (lane j = 0..63).
// Entry: v[r] = x[j + 64*r] (natural order).  Exit: v[r] = X[j + 64*r].
// Twiddles come from the tiny L1-resident global table g_tw2 (coalesced
// along j = lane); inverse uses conjugate-multiply (no extra negates).
template <int INV>
__device__ __forceinline__ void fft512(float2 v[8], float2* S, int j, int bid) {
    // ---- stage 0: Ns = 1 (no twiddle) ----
    fft8<INV>(v);
    bar64(bid);                                    // group's pending reads of S done
    #pragma unroll
    for (int r = 0; r < 8; r++) S[PAD(8 * j + r)] = v[r];
    bar64(bid);
    #pragma unroll
    for (int r = 0; r < 8; r++) v[r] = S[PAD(j + 64 * r)];
    // ---- stage 1: Ns = 8, twiddle exp(-+2*pi*i*r*(j&7)*8/512) ----
    {
        int c = (j & 7) << 3;
        #pragma unroll
        for (int r = 1; r < 8; r++)
            v[r] = cmul_t<INV>(v[r], __ldg(&g_tw2[(r << 6) + c]));
        fft8<INV>(v);
    }
    bar64(bid);
    {
        int idxD = ((j >> 3) << 6) + (j & 7);
        #pragma unroll
        for (int r = 0; r < 8; r++) S[PAD(idxD + 8 * r)] = v[r];
    }
    bar64(bid);
    #pragma unroll
    for (int r = 0; r < 8; r++) v[r] = S[PAD(j + 64 * r)];
    // ---- stage 2: Ns = 64, twiddle exp(-+2*pi*i*r*j/512) ----
    {
        #pragma unroll
        for (int r = 1; r < 8; r++)
            v[r] = cmul_t<INV>(v[r], __ldg(&g_tw2[(r << 6) + j]));
        fft8<INV>(v);
    }
    // exits having just READ S; caller must barrier before writing S.
}

// ---------------------------------------------------------------------------
// Twiddle table (double-precision trig)
// ---------------------------------------------------------------------------
__global__ void k_tw2() {
    int t = threadIdx.x;           // 0..511
    int r = t >> 6, j = t & 63;
    double s, c;
    sincospi(-(double)(r * j) / 256.0, &s, &c);
    g_tw2[t] = make_float2((float)c, (float)s);
}

// ---------------------------------------------------------------------------
// Mask phasor table: g_ME[l][w][a][col] = exp(i*mask) ; layers >= 1 carry the
// 1/512 row-IFFT normalization. Deduplicates the 24x-redundant sincosf work
// the row passes were doing.
// ---------------------------------------------------------------------------
__global__ void k_maskexp(const float* __restrict__ pm) {
    int idx = blockIdx.x * 256 + threadIdx.x;
    if (idx >= NUM_LAYERS * NWL * IMG_ELEMS) return;
    int l = idx / (NWL * IMG_ELEMS);
    float m = pm[idx];
    float s, c;
    sincosf(m, &s, &c);
    float sc = (l == 0) ? 1.0f : (1.0f / 512.0f);
    g_ME[idx] = make_float2(c * sc, s * sc);
}

// ---------------------------------------------------------------------------
// Propagation tables — bit-exact replica of the reference fp32 op chain.
// Stored TRANSPOSED [w][b][a]; pre-scaled by 1/512 (column IFFT norm).
// ---------------------------------------------------------------------------
__device__ __forceinline__ float2 prop_val(float arg, float z) {
    if (arg >= 0.0f) {
        float th = __fmul_rn(__fsqrt_rn(arg), z);
        float s, c;
        sincosf(th, &s, &c);
        return make_float2(c, s);
    } else {
        float dec = __fmul_rn(__fsqrt_rn(-arg), z);
        return make_float2(expf(-dec), 0.0f);
    }
}

__global__ void k_prop() {
    int idx = blockIdx.x * 256 + threadIdx.x;
    if (idx >= NWL * IMG_ELEMS) return;
    int jj = idx & 511;            // FX index a
    int i  = (idx >> 9) & 511;     // FY index b
    int w  = idx >> 18;

    const float dn = (float)(8e-06 * 512.0);
    int ia = (jj < 256) ? jj : jj - 512;
    int ib = (i  < 256) ? i  : i  - 512;
    const float TWO_PI = (float)6.283185307179586;
    float fxa = __fdiv_rn((float)ia, dn);
    float fxb = __fdiv_rn((float)ib, dn);
    float kxa = __fmul_rn(TWO_PI, fxa);
    float kyb = __fmul_rn(TWO_PI, fxb);
    float wl = (w == 0) ? (float)5.32e-07 : ((w == 1) ? (float)6.33e-07 : (float)8.5e-07);
    float k  = __fdiv_rn(TWO_PI, wl);
    float arg = __fsub_rn(__fsub_rn(__fmul_rn(k, k), __fmul_rn(kxa, kxa)),
                          __fmul_rn(kyb, kyb));
    float2 pl = prop_val(arg, (float)0.03);
    float2 pd = prop_val(arg, (float)0.1);
    const float sc = 1.0f / 512.0f;
    float2 pld = cmul(pl, pd);
    g_PLT[idx]  = make_float2(pl.x * sc,  pl.y * sc);
    g_PLDT[idx] = make_float2(pld.x * sc, pld.y * sc);
}

// ---------------------------------------------------------------------------
// Pass A: (x_real + i x_imag) * ME[0]  -> row FFT -> g_bufA
// 256 threads = 4 rows/block (groups use named barriers; no __syncthreads).
// ---------------------------------------------------------------------------
__global__ void __launch_bounds__(256, 4)
k_rowA(const float* __restrict__ xr, const float* __restrict__ xi) {
    __shared__ float2 seg[4 * 577];
    int tid = threadIdx.x;
    int g = tid >> 6, j = tid & 63;
    int rowg = blockIdx.x * 4 + g;                 // global row id: img*512 + a
    int img = rowg >> 9, a = rowg & 511, w = img % 3;
    const float2* __restrict__ merow = g_ME + ((size_t)(w * H + a)) * H;
    size_t base = (size_t)rowg * H;

    float2 v[8];
    #pragma unroll
    for (int r = 0; r < 8; r++) {
        int col = j + (r << 6);
        float2 f = make_float2(xr[base + col], xi[base + col]);
        v[r] = cmul(f, merow[col]);
    }
    fft512<0>(v, seg + g * 577, j, g + 1);
    #pragma unroll
    for (int r = 0; r < 8; r++) g_bufA[base + j + (r << 6)] = v[r];
}

// ---------------------------------------------------------------------------
// Pass C: g_bufB -> row IFFT -> * ME[layer] (carries 1/512) -> row FFT -> g_bufA
// ---------------------------------------------------------------------------
__global__ void __launch_bounds__(256, 4)
k_rowC(int layer) {
    __shared__ float2 seg[4 * 577];
    int tid = threadIdx.x;
    int g = tid >> 6, j = tid & 63;
    int rowg = blockIdx.x * 4 + g;
    int img = rowg >> 9, a = rowg & 511, w = img % 3;
    const float2* __restrict__ merow =
        g_ME + ((size_t)((layer * NWL + w) * H + a)) * H;
    size_t base = (size_t)rowg * H;
    float2* S = seg + g * 577;

    float2 v[8];
    #pragma unroll
    for (int r = 0; r < 8; r++) v[r] = g_bufB[base + j + (r << 6)];
    fft512<1>(v, S, j, g + 1);
    #pragma unroll
    for (int r = 0; r < 8; r++) v[r] = cmul(v[r], merow[j + (r << 6)]);
    fft512<0>(v, S, j, g + 1);
    #pragma unroll
    for (int r = 0; r < 8; r++) g_bufA[base + j + (r << 6)] = v[r];
}

// ---------------------------------------------------------------------------
// Pass D: g_bufB -> row IFFT (x 1/512) -> d_out (interleaved re/im = float2)
// ---------------------------------------------------------------------------
__global__ void __launch_bounds__(256, 4)
k_rowD(float2* __restrict__ out) {
    __shared__ float2 seg[4 * 577];
    int tid = threadIdx.x;
    int g = tid >> 6, j = tid & 63;
    int rowg = blockIdx.x * 4 + g;
    size_t base = (size_t)rowg * H;

    float2 v[8];
    #pragma unroll
    for (int r = 0; r < 8; r++) v[r] = g_bufB[base + j + (r << 6)];
    fft512<1>(v, seg + g * 577, j, g + 1);
    const float sc = 1.0f / 512.0f;
    #pragma unroll
    for (int r = 0; r < 8; r++) {
        float2 t = v[r];
        t.x *= sc; t.y *= sc;
        out[base + j + (r << 6)] = t;
    }
}

// ---------------------------------------------------------------------------
// Pass B: g_bufA -> col FFT -> * P(pre-scaled) -> col IFFT -> g_bufB
// 512 threads; 8 columns/block via padded smem tile; 72*64 blocks.
// launch_bounds(512,2): 64 regs -> 2 blocks/SM (RF exactly full).
// ---------------------------------------------------------------------------
__global__ void __launch_bounds__(512, 2)
k_col(int use_det) {
    __shared__ float2 seg[8 * 577];
    int tid = threadIdx.x;
    int img = blockIdx.x >> 6;                     // 64 col-tiles per image
    int colbase = (blockIdx.x & 63) << 3;
    int w = img % 3;

    const float2* src = g_bufA + (size_t)img * IMG_ELEMS;
    int c = tid & 7, r0 = tid >> 3;                // tile-load mapping
    #pragma unroll
    for (int it = 0; it < 8; it++) {
        int rr = r0 + (it << 6);
        seg[c * 577 + PAD(rr)] = src[(size_t)rr * H + colbase + c];
    }
    __syncthreads();

    int g = tid >> 6, j = tid & 63;                // FFT mapping: group g = column
    float2* S = seg + g * 577;
    float2 v[8];
    #pragma unroll
    for (int r = 0; r < 8; r++) v[r] = S[PAD(j + (r << 6))];

    fft512<0>(v, S, j, g + 1);

    // spectral multiply: element (a = j+64r, b = colbase+g) * P[w][a][b];
    // table stored transposed as [w][b][a] -> coalesced along a; pre-scaled 1/512
    const float2* __restrict__ tab =
        (use_det ? g_PLDT : g_PLT) + ((size_t)(w * H + colbase + g)) * H;
    #pragma unroll
    for (int r = 0; r < 8; r++) v[r] = cmul(v[r], tab[j + (r << 6)]);

    fft512<1>(v, S, j, g + 1);

    __syncthreads();                               // all groups done reading S
    #pragma unroll
    for (int r = 0; r < 8; r++) S[PAD(j + (r << 6))] = v[r];
    __syncthreads();

    float2* dst = g_bufB + (size_t)img * IMG_ELEMS;
    #pragma unroll
    for (int it = 0; it < 8; it++) {
        int rr = r0 + (it << 6);
        dst[(size_t)rr * H + colbase + c] = seg[c * 577 + PAD(rr)];
    }
}

// ---------------------------------------------------------------------------
// Launch: 11 fused passes + 3 small table kernels. Graph-capturable.
// ---------------------------------------------------------------------------
extern "C" void kernel_launch(void* const* d_in, const int* in_sizes, int n_in,
                              void* d_out, int out_size) {
    (void)in_sizes; (void)n_in; (void)out_size;
    const float* xr = (const float*)d_in[0];
    const float* xi = (const float*)d_in[1];
    const float* pm = (const float*)d_in[2];   // [5, 3, 512, 512]

    k_tw2<<<1, 512>>>();
    k_prop<<<(NWL * IMG_ELEMS + 255) / 256, 256>>>();
    k_maskexp<<<(NUM_LAYERS * NWL * IMG_ELEMS + 255) / 256, 256>>>(pm);

    // input + mask0 + row FFT
    k_rowA<<<NIMG * H / 4, 256>>>(xr, xi);

    for (int l = 0; l < NUM_LAYERS; l++) {
        // col FFT * P * col IFFT   (layer 4 folds in prop_det; the
        // intervening ifft2/fft2 pair of the reference is the identity)
        k_col<<<NIMG * 64, 512>>>((l == NUM_LAYERS - 1) ? 1 : 0);
        if (l < NUM_LAYERS - 1) {
            // row IFFT * ME[l+1] (scale folded) * row FFT
            k_rowC<<<NIMG * H / 4, 256>>>(l + 1);
        }
    }

    // final row IFFT -> output (re/im interleaved == float2)
    k_rowD<<<NIMG * H / 4, 256>>>((float2*)d_out);
}